// round 1
// baseline (speedup 1.0000x reference)
#include <cuda_runtime.h>
#include <cuda_bf16.h>
#include <mma.h>
#include <math.h>

using namespace nvcuda;

#define HID   128
#define NREL  8
#define MAXN  100000
#define MAXE  500000
#define TM    32
#define TN    64

// Scratch (static __device__ allocations are the allowed scratch mechanism)
__device__ float g_H [(size_t)NREL * MAXN * HID];  // transformed features per relation
__device__ float g_X0[(size_t)MAXN * HID];         // gathered embeddings / layer input
__device__ float g_X1[(size_t)MAXN * HID];         // layer-1 output
__device__ int   g_cnt[MAXN * NREL];               // per (dst, rel) edge counts

// ---------------- small utility kernels ----------------

__global__ void zero_cnt_kernel(int total) {
    int i = blockIdx.x * blockDim.x + threadIdx.x;
    if (i < total) g_cnt[i] = 0;
}

__global__ void count_kernel(const int* __restrict__ dst,
                             const int* __restrict__ et, int E) {
    int e = blockIdx.x * blockDim.x + threadIdx.x;
    if (e < E) atomicAdd(&g_cnt[dst[e] * NREL + et[e]], 1);
}

__global__ void gather_kernel(const int* __restrict__ ids,
                              const float* __restrict__ emb, int N) {
    int n    = blockIdx.x * (blockDim.x >> 5) + (threadIdx.x >> 5);
    int lane = threadIdx.x & 31;
    if (n < N) {
        const float4* s = (const float4*)(emb + (size_t)ids[n] * HID);
        float4*       d = (float4*)(g_X0 + (size_t)n * HID);
        d[lane] = s[lane];
    }
}

// ---------------- TF32 WMMA GEMM: H[r] = X @ W[r], base = X @ root -------------
// grid: (N/TM, HID/TN, NREL+1), block: 256 threads (8 warps)

template <int LAYER>
__global__ __launch_bounds__(256) void gemm_kernel(const float* __restrict__ W,
                                                   const float* __restrict__ root,
                                                   float* __restrict__ base_ext,
                                                   int N) {
    __shared__ float sA[TM][HID];   // 16 KB
    __shared__ float sB[HID][TN];   // 32 KB   (total 48 KB)

    const float* X    = (LAYER == 1) ? g_X0 : g_X1;
    int          z    = blockIdx.z;
    const float* B    = (z < NREL) ? (W + (size_t)z * HID * HID) : root;
    float*       C    = (z < NREL) ? (g_H + (size_t)z * N * HID)
                                   : ((LAYER == 1) ? g_X1 : base_ext);
    int row0 = blockIdx.x * TM;
    int col0 = blockIdx.y * TN;
    int tid  = threadIdx.x;

    // load A tile: TM x HID -> 1024 float4, 4 per thread
    for (int i = tid; i < TM * HID / 4; i += 256) {
        int r  = i >> 5;          // HID/4 == 32 per row
        int c4 = i & 31;
        float4 v = make_float4(0.f, 0.f, 0.f, 0.f);
        if (row0 + r < N)
            v = ((const float4*)(X + (size_t)(row0 + r) * HID))[c4];
        *(float4*)&sA[r][c4 * 4] = v;
    }
    // load B tile: HID x TN -> 2048 float4, 8 per thread
    for (int i = tid; i < HID * TN / 4; i += 256) {
        int r  = i / (TN / 4);
        int c4 = i % (TN / 4);
        *(float4*)&sB[r][c4 * 4] = ((const float4*)(B + (size_t)r * HID + col0))[c4];
    }
    __syncthreads();

    int warp = tid >> 5;
    int mw   = warp >> 2;   // 0..1 : 16-row strip
    int nw   = warp & 3;    // 0..3 : 16-col strip

    wmma::fragment<wmma::accumulator, 16, 16, 8, float> acc;
    wmma::fill_fragment(acc, 0.0f);
    wmma::fragment<wmma::matrix_a, 16, 16, 8, wmma::precision::tf32, wmma::row_major> a;
    wmma::fragment<wmma::matrix_b, 16, 16, 8, wmma::precision::tf32, wmma::row_major> b;

    #pragma unroll
    for (int k = 0; k < HID; k += 8) {
        wmma::load_matrix_sync(a, &sA[mw * 16][k], HID);
        #pragma unroll
        for (int t = 0; t < a.num_elements; t++) a.x[t] = wmma::__float_to_tf32(a.x[t]);
        wmma::load_matrix_sync(b, &sB[k][nw * 16], TN);
        #pragma unroll
        for (int t = 0; t < b.num_elements; t++) b.x[t] = wmma::__float_to_tf32(b.x[t]);
        wmma::mma_sync(acc, a, b, acc);
    }

    int orow = row0 + mw * 16;
    if (orow < N)
        wmma::store_matrix_sync(C + (size_t)orow * HID + col0 + nw * 16, acc,
                                HID, wmma::mem_row_major);
}

// ---------------- edge scatter: out[dst] += H[et][src] / cnt[dst,et] ----------
// one warp per edge; vectorized fp32 reduction (red.global.add.v4.f32)

template <int LAYER>
__global__ __launch_bounds__(256) void scatter_kernel(const int* __restrict__ src,
                                                      const int* __restrict__ dst,
                                                      const int* __restrict__ et,
                                                      float* __restrict__ out_ext,
                                                      int E, int N) {
    float* out = (LAYER == 1) ? g_X1 : out_ext;
    int e    = blockIdx.x * (blockDim.x >> 5) + (threadIdx.x >> 5);
    int lane = threadIdx.x & 31;
    if (e >= E) return;

    int s = src[e];
    int d = dst[e];
    int r = et[e];
    float inv = 1.0f / (float)g_cnt[d * NREL + r];   // cnt >= 1 for existing edge

    float4 v = ((const float4*)(g_H + ((size_t)r * N + s) * HID))[lane];
    float* o = out + (size_t)d * HID + (size_t)lane * 4;
    asm volatile("red.global.add.v4.f32 [%0], {%1, %2, %3, %4};"
                 :: "l"(o), "f"(v.x * inv), "f"(v.y * inv),
                    "f"(v.z * inv), "f"(v.w * inv)
                 : "memory");
}

// ---------------- activations (bias folded in) ----------------

__global__ void relu_bias_kernel(const float* __restrict__ bias, int total) {
    int i = blockIdx.x * blockDim.x + threadIdx.x;
    if (i < total) {
        float v = g_X1[i] + bias[i & (HID - 1)];
        g_X1[i] = v > 0.f ? v : 0.f;
    }
}

__global__ void sigmoid_bias_kernel(float* __restrict__ X,
                                    const float* __restrict__ bias, int total) {
    int i = blockIdx.x * blockDim.x + threadIdx.x;
    if (i < total) {
        float v = X[i] + bias[i & (HID - 1)];
        X[i] = 1.0f / (1.0f + expf(-v));
    }
}

// ---------------- launch ----------------

extern "C" void kernel_launch(void* const* d_in, const int* in_sizes, int n_in,
                              void* d_out, int out_size) {
    const int*   x_ids = (const int*)d_in[0];
    const int*   eidx  = (const int*)d_in[1];
    const int*   etype = (const int*)d_in[2];
    const float* emb   = (const float*)d_in[3];
    const float* W1    = (const float*)d_in[4];
    const float* root1 = (const float*)d_in[5];
    const float* b1    = (const float*)d_in[6];
    const float* W2    = (const float*)d_in[7];
    const float* root2 = (const float*)d_in[8];
    const float* b2    = (const float*)d_in[9];
    float*       out   = (float*)d_out;

    int N = in_sizes[0];
    int E = in_sizes[2];
    const int* src = eidx;
    const int* dst = eidx + E;

    int total_feat = N * HID;

    // counts (shared by both layers)
    zero_cnt_kernel<<<(N * NREL + 255) / 256, 256>>>(N * NREL);
    count_kernel<<<(E + 255) / 256, 256>>>(dst, etype, E);

    // embedding gather -> X0
    gather_kernel<<<(N + 7) / 8, 256>>>(x_ids, emb, N);

    dim3 ggrid((N + TM - 1) / TM, HID / TN, NREL + 1);

    // ---- layer 1 ----
    gemm_kernel<1><<<ggrid, 256>>>(W1, root1, nullptr, N);
    scatter_kernel<1><<<(E + 7) / 8, 256>>>(src, dst, etype, nullptr, E, N);
    relu_bias_kernel<<<(total_feat + 255) / 256, 256>>>(b1, total_feat);

    // ---- layer 2 ----
    gemm_kernel<2><<<ggrid, 256>>>(W2, root2, out, N);
    scatter_kernel<2><<<(E + 7) / 8, 256>>>(src, dst, etype, out, E, N);
    sigmoid_bias_kernel<<<(total_feat + 255) / 256, 256>>>(out, b2, total_feat);
}

// round 2
// speedup vs baseline: 1.9896x; 1.9896x over previous
#include <cuda_runtime.h>
#include <cuda_bf16.h>
#include <mma.h>
#include <math.h>

using namespace nvcuda;

#define HID   128
#define NREL  8
#define MAXN  100000
#define BM    128
#define LDA   (HID + 4)          // padded smem stride (floats)
#define SMEM_BYTES ((BM + HID) * LDA * 4)

// Scratch (static __device__ arrays = allowed scratch)
__device__ float g_H [(size_t)NREL * MAXN * HID];  // transformed features per relation
__device__ float g_X0[(size_t)MAXN * HID];         // gathered embeddings
__device__ float g_X1[(size_t)MAXN * HID];         // layer-1 output
__device__ int   g_cnt[MAXN * NREL];               // per (dst, rel) edge counts

// ---------------- small utility kernels ----------------

__global__ void zero_cnt_kernel(int total) {
    int i = blockIdx.x * blockDim.x + threadIdx.x;
    if (i < total) g_cnt[i] = 0;
}

__global__ void count_kernel(const int* __restrict__ dst,
                             const int* __restrict__ et, int E) {
    int e = blockIdx.x * blockDim.x + threadIdx.x;
    if (e < E) atomicAdd(&g_cnt[dst[e] * NREL + et[e]], 1);
}

__global__ void gather_kernel(const int* __restrict__ ids,
                              const float* __restrict__ emb, int N) {
    int n    = blockIdx.x * (blockDim.x >> 5) + (threadIdx.x >> 5);
    int lane = threadIdx.x & 31;
    if (n < N) {
        const float4* s = (const float4*)(emb + (size_t)ids[n] * HID);
        float4*       d = (float4*)(g_X0 + (size_t)n * HID);
        d[lane] = s[lane];
    }
}

// ---------------- TF32 WMMA GEMM ----------------
// One block = 128 output rows x full 128 cols. A loaded to smem ONCE,
// then loop z = 0..8 over the 9 weight matrices (8 relations + root).
// 8 warps in a 4x2 layout, each computes a 32x64 warp tile (2x4 frags).

template <int LAYER>
__global__ __launch_bounds__(256) void gemm_kernel(const float* __restrict__ W,
                                                   const float* __restrict__ root,
                                                   float* __restrict__ base_ext,
                                                   int N) {
    extern __shared__ float smem[];
    float* sA = smem;                 // [BM][LDA]
    float* sB = smem + BM * LDA;      // [HID][LDA]

    const float* X = (LAYER == 1) ? g_X0 : g_X1;
    float* baseC   = (LAYER == 1) ? g_X1 : base_ext;

    int row0 = blockIdx.x * BM;
    int tid  = threadIdx.x;

    // ---- load A tile once: BM x HID, convert to tf32 at store ----
    for (int i = tid; i < BM * HID / 4; i += 256) {
        int r  = i >> 5;                 // 32 float4 per row
        int c4 = i & 31;
        float4 v = make_float4(0.f, 0.f, 0.f, 0.f);
        if (row0 + r < N)
            v = ((const float4*)(X + (size_t)(row0 + r) * HID))[c4];
        float* d = sA + r * LDA + c4 * 4;
        d[0] = wmma::__float_to_tf32(v.x);
        d[1] = wmma::__float_to_tf32(v.y);
        d[2] = wmma::__float_to_tf32(v.z);
        d[3] = wmma::__float_to_tf32(v.w);
    }
    __syncthreads();

    int warp = tid >> 5;
    int rw   = warp >> 1;   // 0..3 : 32-row strip
    int cw   = warp & 1;    // 0..1 : 64-col strip

    for (int z = 0; z < NREL + 1; z++) {
        const float* B = (z < NREL) ? (W + (size_t)z * HID * HID) : root;
        float*       C = (z < NREL) ? (g_H + (size_t)z * N * HID) : baseC;

        // ---- load B_z: HID x HID ----
        for (int i = tid; i < HID * HID / 4; i += 256) {
            int r  = i >> 5;
            int c4 = i & 31;
            float4 v = ((const float4*)(B + (size_t)r * HID))[c4];
            float* d = sB + r * LDA + c4 * 4;
            d[0] = wmma::__float_to_tf32(v.x);
            d[1] = wmma::__float_to_tf32(v.y);
            d[2] = wmma::__float_to_tf32(v.z);
            d[3] = wmma::__float_to_tf32(v.w);
        }
        __syncthreads();

        wmma::fragment<wmma::accumulator, 16, 16, 8, float> acc[2][4];
        #pragma unroll
        for (int mi = 0; mi < 2; mi++)
            #pragma unroll
            for (int ni = 0; ni < 4; ni++)
                wmma::fill_fragment(acc[mi][ni], 0.0f);

        wmma::fragment<wmma::matrix_a, 16, 16, 8, wmma::precision::tf32, wmma::row_major> a[2];
        wmma::fragment<wmma::matrix_b, 16, 16, 8, wmma::precision::tf32, wmma::row_major> b[4];

        const float* aBase = sA + (rw * 32) * LDA;
        const float* bBase = sB + cw * 64;

        #pragma unroll
        for (int k = 0; k < HID; k += 8) {
            #pragma unroll
            for (int mi = 0; mi < 2; mi++)
                wmma::load_matrix_sync(a[mi], aBase + mi * 16 * LDA + k, LDA);
            #pragma unroll
            for (int ni = 0; ni < 4; ni++)
                wmma::load_matrix_sync(b[ni], bBase + k * LDA + ni * 16, LDA);
            #pragma unroll
            for (int mi = 0; mi < 2; mi++)
                #pragma unroll
                for (int ni = 0; ni < 4; ni++)
                    wmma::mma_sync(acc[mi][ni], a[mi], b[ni], acc[mi][ni]);
        }

        // ---- store (N is a multiple of 16, so frag rows are all-or-nothing) ----
        #pragma unroll
        for (int mi = 0; mi < 2; mi++) {
            int orow = row0 + rw * 32 + mi * 16;
            if (orow + 16 <= N) {
                #pragma unroll
                for (int ni = 0; ni < 4; ni++)
                    wmma::store_matrix_sync(C + (size_t)orow * HID + cw * 64 + ni * 16,
                                            acc[mi][ni], HID, wmma::mem_row_major);
            }
        }
        __syncthreads();   // all reads of sB done before next z overwrites it
    }
}

// ---------------- edge scatter: out[dst] += H[et][src] / cnt[dst,et] ----------

template <int LAYER>
__global__ __launch_bounds__(256) void scatter_kernel(const int* __restrict__ src,
                                                      const int* __restrict__ dst,
                                                      const int* __restrict__ et,
                                                      float* __restrict__ out_ext,
                                                      int E, int N) {
    float* out = (LAYER == 1) ? g_X1 : out_ext;
    int e    = blockIdx.x * (blockDim.x >> 5) + (threadIdx.x >> 5);
    int lane = threadIdx.x & 31;
    if (e >= E) return;

    int s = src[e];
    int d = dst[e];
    int r = et[e];
    float inv = 1.0f / (float)g_cnt[d * NREL + r];

    float4 v = ((const float4*)(g_H + ((size_t)r * N + s) * HID))[lane];
    float* o = out + (size_t)d * HID + (size_t)lane * 4;
    asm volatile("red.global.add.v4.f32 [%0], {%1, %2, %3, %4};"
                 :: "l"(o), "f"(v.x * inv), "f"(v.y * inv),
                    "f"(v.z * inv), "f"(v.w * inv)
                 : "memory");
}

// ---------------- activations (bias folded in) ----------------

__global__ void relu_bias_kernel(const float* __restrict__ bias, int total) {
    int i = blockIdx.x * blockDim.x + threadIdx.x;
    if (i < total) {
        float v = g_X1[i] + bias[i & (HID - 1)];
        g_X1[i] = v > 0.f ? v : 0.f;
    }
}

__global__ void sigmoid_bias_kernel(float* __restrict__ X,
                                    const float* __restrict__ bias, int total) {
    int i = blockIdx.x * blockDim.x + threadIdx.x;
    if (i < total) {
        float v = X[i] + bias[i & (HID - 1)];
        X[i] = 1.0f / (1.0f + expf(-v));
    }
}

// ---------------- launch ----------------

extern "C" void kernel_launch(void* const* d_in, const int* in_sizes, int n_in,
                              void* d_out, int out_size) {
    const int*   x_ids = (const int*)d_in[0];
    const int*   eidx  = (const int*)d_in[1];
    const int*   etype = (const int*)d_in[2];
    const float* emb   = (const float*)d_in[3];
    const float* W1    = (const float*)d_in[4];
    const float* root1 = (const float*)d_in[5];
    const float* b1    = (const float*)d_in[6];
    const float* W2    = (const float*)d_in[7];
    const float* root2 = (const float*)d_in[8];
    const float* b2    = (const float*)d_in[9];
    float*       out   = (float*)d_out;

    int N = in_sizes[0];
    int E = in_sizes[2];
    const int* src = eidx;
    const int* dst = eidx + E;
    int total_feat = N * HID;

    cudaFuncSetAttribute(gemm_kernel<1>, cudaFuncAttributeMaxDynamicSharedMemorySize, SMEM_BYTES);
    cudaFuncSetAttribute(gemm_kernel<2>, cudaFuncAttributeMaxDynamicSharedMemorySize, SMEM_BYTES);

    zero_cnt_kernel<<<(N * NREL + 255) / 256, 256>>>(N * NREL);
    count_kernel<<<(E + 255) / 256, 256>>>(dst, etype, E);
    gather_kernel<<<(N + 7) / 8, 256>>>(x_ids, emb, N);

    int gblocks = (N + BM - 1) / BM;

    // ---- layer 1 ----
    gemm_kernel<1><<<gblocks, 256, SMEM_BYTES>>>(W1, root1, nullptr, N);
    scatter_kernel<1><<<(E + 7) / 8, 256>>>(src, dst, etype, nullptr, E, N);
    relu_bias_kernel<<<(total_feat + 255) / 256, 256>>>(b1, total_feat);

    // ---- layer 2 ----
    gemm_kernel<2><<<gblocks, 256, SMEM_BYTES>>>(W2, root2, out, N);
    scatter_kernel<2><<<(E + 7) / 8, 256>>>(src, dst, etype, out, E, N);
    sigmoid_bias_kernel<<<(total_feat + 255) / 256, 256>>>(out, b2, total_feat);
}

// round 3
// speedup vs baseline: 2.4030x; 1.2078x over previous
#include <cuda_runtime.h>
#include <cuda_bf16.h>
#include <mma.h>
#include <math.h>

using namespace nvcuda;

#define HID   128
#define NREL  8
#define MAXN  100000
#define BM    256
#define NTHR  512
#define LDA   (HID + 4)          // padded smem stride (floats)
#define SMEM_BYTES ((BM + HID) * LDA * 4)   // 135KB + 67.6KB = 202.8KB

// Scratch (static __device__ arrays = allowed scratch)
__device__ float g_H [(size_t)NREL * MAXN * HID];  // transformed features per relation
__device__ float g_X0[(size_t)MAXN * HID];         // gathered embeddings
__device__ float g_X1[(size_t)MAXN * HID];         // layer-1 output
__device__ int   g_cnt[MAXN * NREL];               // per (dst, rel) edge counts

// ---------------- small utility kernels ----------------

__global__ void zero_cnt_kernel(int total) {
    int i = blockIdx.x * blockDim.x + threadIdx.x;
    if (i < total) g_cnt[i] = 0;
}

__global__ void count_kernel(const int* __restrict__ dst,
                             const int* __restrict__ et, int E) {
    int e = blockIdx.x * blockDim.x + threadIdx.x;
    if (e < E) atomicAdd(&g_cnt[dst[e] * NREL + et[e]], 1);
}

__global__ void gather_kernel(const int* __restrict__ ids,
                              const float* __restrict__ emb, int N) {
    int n    = blockIdx.x * (blockDim.x >> 5) + (threadIdx.x >> 5);
    int lane = threadIdx.x & 31;
    if (n < N) {
        const float4* s = (const float4*)(emb + (size_t)ids[n] * HID);
        float4*       d = (float4*)(g_X0 + (size_t)n * HID);
        d[lane] = s[lane];
    }
}

// ---------------- TF32 WMMA GEMM ----------------
// One block = 256 rows x 128 cols, 512 threads (16 warps, 8x2 layout).
// A tile loaded to smem once; loop z over 9 weight matrices.
// Each warp: 32x64 tile = 2x4 accumulator fragments.

template <int LAYER>
__global__ __launch_bounds__(NTHR) void gemm_kernel(const float* __restrict__ W,
                                                    const float* __restrict__ root,
                                                    float* __restrict__ base_ext,
                                                    int N) {
    extern __shared__ float smem[];
    float* sA = smem;                 // [BM][LDA]
    float* sB = smem + BM * LDA;      // [HID][LDA]

    const float* X = (LAYER == 1) ? g_X0 : g_X1;
    float* baseC   = (LAYER == 1) ? g_X1 : base_ext;

    int row0 = blockIdx.x * BM;
    int tid  = threadIdx.x;

    // ---- load A tile once: BM x HID (16 float4 per thread) ----
    for (int i = tid; i < BM * HID / 4; i += NTHR) {
        int r  = i >> 5;                 // 32 float4 per row
        int c4 = i & 31;
        float4 v = make_float4(0.f, 0.f, 0.f, 0.f);
        if (row0 + r < N)
            v = ((const float4*)(X + (size_t)(row0 + r) * HID))[c4];
        float* d = sA + r * LDA + c4 * 4;
        d[0] = wmma::__float_to_tf32(v.x);
        d[1] = wmma::__float_to_tf32(v.y);
        d[2] = wmma::__float_to_tf32(v.z);
        d[3] = wmma::__float_to_tf32(v.w);
    }
    __syncthreads();

    int warp = tid >> 5;
    int rw   = warp >> 1;   // 0..7 : 32-row strip
    int cw   = warp & 1;    // 0..1 : 64-col strip

    for (int z = 0; z < NREL + 1; z++) {
        const float* B = (z < NREL) ? (W + (size_t)z * HID * HID) : root;
        float*       C = (z < NREL) ? (g_H + (size_t)z * N * HID) : baseC;

        // ---- load B_z: HID x HID (8 float4 per thread) ----
        for (int i = tid; i < HID * HID / 4; i += NTHR) {
            int r  = i >> 5;
            int c4 = i & 31;
            float4 v = ((const float4*)(B + (size_t)r * HID))[c4];
            float* d = sB + r * LDA + c4 * 4;
            d[0] = wmma::__float_to_tf32(v.x);
            d[1] = wmma::__float_to_tf32(v.y);
            d[2] = wmma::__float_to_tf32(v.z);
            d[3] = wmma::__float_to_tf32(v.w);
        }
        __syncthreads();

        wmma::fragment<wmma::accumulator, 16, 16, 8, float> acc[2][4];
        #pragma unroll
        for (int mi = 0; mi < 2; mi++)
            #pragma unroll
            for (int ni = 0; ni < 4; ni++)
                wmma::fill_fragment(acc[mi][ni], 0.0f);

        wmma::fragment<wmma::matrix_a, 16, 16, 8, wmma::precision::tf32, wmma::row_major> a[2];
        wmma::fragment<wmma::matrix_b, 16, 16, 8, wmma::precision::tf32, wmma::row_major> b[4];

        const float* aBase = sA + (rw * 32) * LDA;
        const float* bBase = sB + cw * 64;

        #pragma unroll
        for (int k = 0; k < HID; k += 8) {
            #pragma unroll
            for (int mi = 0; mi < 2; mi++)
                wmma::load_matrix_sync(a[mi], aBase + mi * 16 * LDA + k, LDA);
            #pragma unroll
            for (int ni = 0; ni < 4; ni++)
                wmma::load_matrix_sync(b[ni], bBase + k * LDA + ni * 16, LDA);
            #pragma unroll
            for (int mi = 0; mi < 2; mi++)
                #pragma unroll
                for (int ni = 0; ni < 4; ni++)
                    wmma::mma_sync(acc[mi][ni], a[mi], b[ni], acc[mi][ni]);
        }

        // ---- store (N is a multiple of 16) ----
        #pragma unroll
        for (int mi = 0; mi < 2; mi++) {
            int orow = row0 + rw * 32 + mi * 16;
            if (orow + 16 <= N) {
                #pragma unroll
                for (int ni = 0; ni < 4; ni++)
                    wmma::store_matrix_sync(C + (size_t)orow * HID + cw * 64 + ni * 16,
                                            acc[mi][ni], HID, wmma::mem_row_major);
            }
        }
        __syncthreads();   // all reads of sB done before next z overwrites it
    }
}

// ---------------- edge scatter: out[dst] += H[et][src] / cnt[dst,et] ----------

template <int LAYER>
__global__ __launch_bounds__(256) void scatter_kernel(const int* __restrict__ src,
                                                      const int* __restrict__ dst,
                                                      const int* __restrict__ et,
                                                      float* __restrict__ out_ext,
                                                      int E, int N) {
    float* out = (LAYER == 1) ? g_X1 : out_ext;
    int e    = blockIdx.x * (blockDim.x >> 5) + (threadIdx.x >> 5);
    int lane = threadIdx.x & 31;
    if (e >= E) return;

    int s = src[e];
    int d = dst[e];
    int r = et[e];
    float inv = 1.0f / (float)g_cnt[d * NREL + r];

    float4 v = ((const float4*)(g_H + ((size_t)r * N + s) * HID))[lane];
    float* o = out + (size_t)d * HID + (size_t)lane * 4;
    asm volatile("red.global.add.v4.f32 [%0], {%1, %2, %3, %4};"
                 :: "l"(o), "f"(v.x * inv), "f"(v.y * inv),
                    "f"(v.z * inv), "f"(v.w * inv)
                 : "memory");
}

// ---------------- activations (bias folded in) ----------------

__global__ void relu_bias_kernel(const float* __restrict__ bias, int total) {
    int i = blockIdx.x * blockDim.x + threadIdx.x;
    if (i < total) {
        float v = g_X1[i] + bias[i & (HID - 1)];
        g_X1[i] = v > 0.f ? v : 0.f;
    }
}

__global__ void sigmoid_bias_kernel(float* __restrict__ X,
                                    const float* __restrict__ bias, int total) {
    int i = blockIdx.x * blockDim.x + threadIdx.x;
    if (i < total) {
        float v = X[i] + bias[i & (HID - 1)];
        X[i] = 1.0f / (1.0f + expf(-v));
    }
}

// ---------------- launch ----------------

extern "C" void kernel_launch(void* const* d_in, const int* in_sizes, int n_in,
                              void* d_out, int out_size) {
    const int*   x_ids = (const int*)d_in[0];
    const int*   eidx  = (const int*)d_in[1];
    const int*   etype = (const int*)d_in[2];
    const float* emb   = (const float*)d_in[3];
    const float* W1    = (const float*)d_in[4];
    const float* root1 = (const float*)d_in[5];
    const float* b1    = (const float*)d_in[6];
    const float* W2    = (const float*)d_in[7];
    const float* root2 = (const float*)d_in[8];
    const float* b2    = (const float*)d_in[9];
    float*       out   = (float*)d_out;

    int N = in_sizes[0];
    int E = in_sizes[2];
    const int* src = eidx;
    const int* dst = eidx + E;
    int total_feat = N * HID;

    cudaFuncSetAttribute(gemm_kernel<1>, cudaFuncAttributeMaxDynamicSharedMemorySize, SMEM_BYTES);
    cudaFuncSetAttribute(gemm_kernel<2>, cudaFuncAttributeMaxDynamicSharedMemorySize, SMEM_BYTES);

    zero_cnt_kernel<<<(N * NREL + 255) / 256, 256>>>(N * NREL);
    count_kernel<<<(E + 255) / 256, 256>>>(dst, etype, E);
    gather_kernel<<<(N + 7) / 8, 256>>>(x_ids, emb, N);

    int gblocks = (N + BM - 1) / BM;

    // ---- layer 1 ----
    gemm_kernel<1><<<gblocks, NTHR, SMEM_BYTES>>>(W1, root1, nullptr, N);
    scatter_kernel<1><<<(E + 7) / 8, 256>>>(src, dst, etype, nullptr, E, N);
    relu_bias_kernel<<<(total_feat + 255) / 256, 256>>>(b1, total_feat);

    // ---- layer 2 ----
    gemm_kernel<2><<<gblocks, NTHR, SMEM_BYTES>>>(W2, root2, out, N);
    scatter_kernel<2><<<(E + 7) / 8, 256>>>(src, dst, etype, out, E, N);
    sigmoid_bias_kernel<<<(total_feat + 255) / 256, 256>>>(out, b2, total_feat);
}